// round 1
// baseline (speedup 1.0000x reference)
#include <cuda_runtime.h>

#define BATCH 1024
#define FF 128
#define EE 256
#define HH 8
#define DD 32

// shared memory layout (floats)
constexpr int XS_N  = FF * EE;      // 32768  X tile
constexpr int QS_N  = FF * DD;      // 4096   Q (row-major [128][32])
constexpr int KT_LD = 132;          // padded leading dim for K^T
constexpr int KT_N  = DD * KT_LD;   // 4224   K^T ([32][132])
constexpr int VS_N  = FF * DD;      // 4096   V (row-major [128][32])
constexpr int PS_N  = 8 * FF;       // 1024   per-warp softmax row
constexpr int SMEM_FLOATS = XS_N + QS_N + KT_N + VS_N + PS_N;   // 46208
constexpr int SMEM_BYTES  = SMEM_FLOATS * 4;                    // 184832

__global__ __launch_bounds__(256, 1)
void fused_mha_kernel(const float* __restrict__ X,
                      const float* __restrict__ Wq,
                      const float* __restrict__ Wk,
                      const float* __restrict__ Wv,
                      const float* __restrict__ Wr,
                      float* __restrict__ out)
{
    extern __shared__ float sm[];
    float* Xs  = sm;
    float* Qs  = Xs + XS_N;
    float* Kts = Qs + QS_N;
    float* Vs  = Kts + KT_N;
    float* ps  = Vs + VS_N;

    const int b    = blockIdx.x;
    const int tid  = threadIdx.x;
    const int lane = tid & 31;
    const int w    = tid >> 5;        // warp id 0..7

    // ---- stage X_b into smem (coalesced float4) ----
    const float4* Xg  = reinterpret_cast<const float4*>(X + (size_t)b * FF * EE);
    float4*       Xs4 = reinterpret_cast<float4*>(Xs);
    #pragma unroll
    for (int i = tid; i < XS_N / 4; i += 256) Xs4[i] = Xg[i];
    __syncthreads();

    float* outb = out + (size_t)b * FF * EE;

    const int j  = lane;   // column within head (0..31)
    const int rg = w;      // row group (16 rows each)

    for (int h = 0; h < HH; ++h) {
        // =========== QKV projection: rows rg*16..rg*16+15, col j ===========
        float aq[16], ak[16], av[16];
        #pragma unroll
        for (int t = 0; t < 16; ++t) { aq[t] = 0.f; ak[t] = 0.f; av[t] = 0.f; }

        const int wcol = h * DD + j;
        for (int k4 = 0; k4 < EE; k4 += 4) {
            float wqv[4], wkv[4], wvv[4];
            #pragma unroll
            for (int kk = 0; kk < 4; ++kk) {
                wqv[kk] = Wq[(k4 + kk) * EE + wcol];
                wkv[kk] = Wk[(k4 + kk) * EE + wcol];
                wvv[kk] = Wv[(k4 + kk) * EE + wcol];
            }
            #pragma unroll
            for (int t = 0; t < 16; ++t) {
                const float4 x = *reinterpret_cast<const float4*>(&Xs[(rg * 16 + t) * EE + k4]);
                aq[t] = fmaf(x.x, wqv[0], aq[t]); aq[t] = fmaf(x.y, wqv[1], aq[t]);
                aq[t] = fmaf(x.z, wqv[2], aq[t]); aq[t] = fmaf(x.w, wqv[3], aq[t]);
                ak[t] = fmaf(x.x, wkv[0], ak[t]); ak[t] = fmaf(x.y, wkv[1], ak[t]);
                ak[t] = fmaf(x.z, wkv[2], ak[t]); ak[t] = fmaf(x.w, wkv[3], ak[t]);
                av[t] = fmaf(x.x, wvv[0], av[t]); av[t] = fmaf(x.y, wvv[1], av[t]);
                av[t] = fmaf(x.z, wvv[2], av[t]); av[t] = fmaf(x.w, wvv[3], av[t]);
            }
        }

        // wait for previous head's attention readers before overwriting Q/K/V
        __syncthreads();
        #pragma unroll
        for (int t = 0; t < 16; ++t) {
            const int r = rg * 16 + t;
            Qs[r * DD + j]      = aq[t];
            Kts[j * KT_LD + r]  = ak[t];   // transposed store (4-way conflict, cheap)
            Vs[r * DD + j]      = av[t];
        }
        __syncthreads();

        // =========== attention: warp w owns rows w*16..w*16+15 ===========
        float* pw = ps + w * FF;
        for (int ii = 0; ii < 16; ++ii) {
            const int i = w * 16 + ii;
            // scores: lane covers j4 = 4*lane..4*lane+3
            float s0 = 0.f, s1 = 0.f, s2 = 0.f, s3 = 0.f;
            #pragma unroll
            for (int d = 0; d < DD; ++d) {
                const float  q  = Qs[i * DD + d];                       // broadcast
                const float4 kk = *reinterpret_cast<const float4*>(&Kts[d * KT_LD + 4 * lane]);
                s0 = fmaf(q, kk.x, s0); s1 = fmaf(q, kk.y, s1);
                s2 = fmaf(q, kk.z, s2); s3 = fmaf(q, kk.w, s3);
            }
            // softmax over 128 (distributed across lanes)
            float m = fmaxf(fmaxf(s0, s1), fmaxf(s2, s3));
            #pragma unroll
            for (int off = 16; off; off >>= 1) m = fmaxf(m, __shfl_xor_sync(0xffffffffu, m, off));
            const float e0 = __expf(s0 - m), e1 = __expf(s1 - m),
                        e2 = __expf(s2 - m), e3 = __expf(s3 - m);
            float sum = e0 + e1 + e2 + e3;
            #pragma unroll
            for (int off = 16; off; off >>= 1) sum += __shfl_xor_sync(0xffffffffu, sum, off);
            const float rs = 1.0f / sum;
            *reinterpret_cast<float4*>(&pw[4 * lane]) = make_float4(e0 * rs, e1 * rs, e2 * rs, e3 * rs);
            __syncwarp();

            // out row i, lane = d'
            float acc = 0.f;
            #pragma unroll 8
            for (int jj = 0; jj < FF; jj += 4) {
                const float4 p = *reinterpret_cast<const float4*>(&pw[jj]);  // broadcast
                acc = fmaf(p.x, Vs[(jj + 0) * DD + lane], acc);
                acc = fmaf(p.y, Vs[(jj + 1) * DD + lane], acc);
                acc = fmaf(p.z, Vs[(jj + 2) * DD + lane], acc);
                acc = fmaf(p.w, Vs[(jj + 3) * DD + lane], acc);
            }
            outb[i * EE + h * DD + lane] = acc;   // coalesced 128B per warp
            __syncwarp();                          // protect pw before next row's write
        }
    }
    __syncthreads();   // all attention outputs globally visible within CTA

    // =========== residual GEMM + ReLU: thread owns column c = tid ===========
    const int c = tid;
    for (int g = 0; g < 8; ++g) {
        float acc[16];
        #pragma unroll
        for (int t = 0; t < 16; ++t) acc[t] = 0.f;
        for (int k4 = 0; k4 < EE; k4 += 4) {
            const float w0 = Wr[(k4 + 0) * EE + c];
            const float w1 = Wr[(k4 + 1) * EE + c];
            const float w2 = Wr[(k4 + 2) * EE + c];
            const float w3 = Wr[(k4 + 3) * EE + c];
            #pragma unroll
            for (int t = 0; t < 16; ++t) {
                const float4 x = *reinterpret_cast<const float4*>(&Xs[(g * 16 + t) * EE + k4]);
                acc[t] = fmaf(x.x, w0, acc[t]); acc[t] = fmaf(x.y, w1, acc[t]);
                acc[t] = fmaf(x.z, w2, acc[t]); acc[t] = fmaf(x.w, w3, acc[t]);
            }
        }
        #pragma unroll
        for (int t = 0; t < 16; ++t) {
            const int r = g * 16 + t;
            const float v = outb[r * EE + c] + acc[t];
            outb[r * EE + c] = v > 0.f ? v : 0.f;
        }
    }
}

extern "C" void kernel_launch(void* const* d_in, const int* in_sizes, int n_in,
                              void* d_out, int out_size)
{
    const float* X  = (const float*)d_in[0];
    const float* Wq = (const float*)d_in[1];
    const float* Wk = (const float*)d_in[2];
    const float* Wv = (const float*)d_in[3];
    const float* Wr = (const float*)d_in[4];
    float* out = (float*)d_out;

    cudaFuncSetAttribute(fused_mha_kernel,
                         cudaFuncAttributeMaxDynamicSharedMemorySize, SMEM_BYTES);
    fused_mha_kernel<<<BATCH, 256, SMEM_BYTES>>>(X, Wq, Wk, Wv, Wr, out);
}